// round 3
// baseline (speedup 1.0000x reference)
#include <cuda_runtime.h>
#include <cstdint>

#define B_     8
#define S_     1024
#define D_     512
#define H_     8
#define HD_    64
#define FF_    2048
#define STEPS_ 64
#define CAP_   1088
#define MTOK   (B_*S_)   /* 8192 */
#define NBLK   128

// ---------------- device scratch (no cudaMalloc allowed) ----------------
__device__ float g_qkv [MTOK*1536];   // prefill QKV
__device__ float g_attn[MTOK*D_];     // prefill attention output
__device__ float g_pre [MTOK*D_];     // pre-LN buffer
__device__ float g_h   [MTOK*D_];     // post-LN1 hidden
__device__ float g_hff [MTOK*FF_];    // MLP hidden
__device__ float g_kc  [B_*CAP_*D_];  // K cache
__device__ float g_vc  [B_*CAP_*D_];  // V cache
__device__ float g_qt  [B_*D_];       // decode q
__device__ float g_hfft[B_*FF_];      // decode MLP hidden
__device__ float g_t1  [B_*D_];       // decode temp
__device__ float g_op  [2*64*64];     // attention partial O  [part][b*8+h][64]
__device__ float g_ml  [2*64*2];      // attention partial m,l
__device__ unsigned g_flags[NBLK];    // distributed barrier flags

// ---------------- reductions ----------------
__device__ __forceinline__ float warpRedSum(float v) {
#pragma unroll
    for (int o = 16; o; o >>= 1) v += __shfl_xor_sync(0xffffffffu, v, o);
    return v;
}
__device__ __forceinline__ float warpRedMax(float v) {
#pragma unroll
    for (int o = 16; o; o >>= 1) v = fmaxf(v, __shfl_xor_sync(0xffffffffu, v, o));
    return v;
}

// ---------------- distributed global barrier ----------------
__device__ __forceinline__ unsigned ld_acq(const unsigned* p) {
    unsigned v;
    asm volatile("ld.acquire.gpu.u32 %0, [%1];" : "=r"(v) : "l"(p) : "memory");
    return v;
}
__device__ __forceinline__ void st_rel(unsigned* p, unsigned v) {
    asm volatile("st.release.gpu.u32 [%0], %1;" :: "l"(p), "r"(v) : "memory");
}
__device__ __forceinline__ void gbar(unsigned& target, int tid, int bid) {
    __threadfence();
    __syncthreads();
    target += 1;
    if (tid == 0) st_rel(&g_flags[bid], target);
    if (tid < NBLK) {
        while ((int)(ld_acq(&g_flags[tid]) - target) < 0) __nanosleep(40);
    }
    __syncthreads();
}

// ---------------- SGEMM (NT): C[m,n] = sum_k A[m,k]*B[n,k] (+bias,+res,relu) ----------------
// BM=BN=128, BK=16, 256 threads; per-thread tile split 4+4 in both dims for
// conflict-free LDS.128 (phase of 8 lanes covers contiguous 128B).
template<int BIAS, int RELU, int RES>
__global__ void __launch_bounds__(256) sgemm_nt(
    const float* __restrict__ A, const float* __restrict__ Bm,
    const float* __restrict__ bias, const float* __restrict__ R,
    float* __restrict__ C, int M, int N, int K)
{
    __shared__ float As[16][132];
    __shared__ float Bs[16][132];
    const int tid = threadIdx.x;
    const int m0 = blockIdx.y * 128;
    const int n0 = blockIdx.x * 128;
    const int tx = tid & 15, ty = tid >> 4;
    const int r0 = ty * 4, c0 = tx * 4;
    const int lrow = tid >> 2;
    const int lk4  = (tid & 3) * 4;

    float acc[8][8];
#pragma unroll
    for (int i = 0; i < 8; i++)
#pragma unroll
        for (int j = 0; j < 8; j++) acc[i][j] = 0.f;

    for (int k0 = 0; k0 < K; k0 += 16) {
#pragma unroll
        for (int half = 0; half < 2; half++) {
            int row = lrow + half * 64;
            float4 a = *(const float4*)(A + (size_t)(m0 + row) * K + k0 + lk4);
            As[lk4 + 0][row] = a.x; As[lk4 + 1][row] = a.y;
            As[lk4 + 2][row] = a.z; As[lk4 + 3][row] = a.w;
            float4 b = *(const float4*)(Bm + (size_t)(n0 + row) * K + k0 + lk4);
            Bs[lk4 + 0][row] = b.x; Bs[lk4 + 1][row] = b.y;
            Bs[lk4 + 2][row] = b.z; Bs[lk4 + 3][row] = b.w;
        }
        __syncthreads();
#pragma unroll
        for (int kk = 0; kk < 16; kk++) {
            float af[8], bf[8];
            *(float4*)(af)     = *(const float4*)(&As[kk][r0]);
            *(float4*)(af + 4) = *(const float4*)(&As[kk][r0 + 64]);
            *(float4*)(bf)     = *(const float4*)(&Bs[kk][c0]);
            *(float4*)(bf + 4) = *(const float4*)(&Bs[kk][c0 + 64]);
#pragma unroll
            for (int i = 0; i < 8; i++)
#pragma unroll
                for (int j = 0; j < 8; j++)
                    acc[i][j] = fmaf(af[i], bf[j], acc[i][j]);
        }
        __syncthreads();
    }

    float bl[8];
#pragma unroll
    for (int j = 0; j < 8; j++)
        bl[j] = BIAS ? bias[n0 + c0 + (j < 4 ? j : 60 + j)] : 0.f;

#pragma unroll
    for (int i = 0; i < 8; i++) {
        const int row = m0 + r0 + (i < 4 ? i : 60 + i);
        const size_t rowoff = (size_t)row * N + n0;
#pragma unroll
        for (int jg = 0; jg < 2; jg++) {
            const int cb = c0 + jg * 64;
            float t0 = acc[i][jg * 4 + 0] + bl[jg * 4 + 0];
            float t1 = acc[i][jg * 4 + 1] + bl[jg * 4 + 1];
            float t2 = acc[i][jg * 4 + 2] + bl[jg * 4 + 2];
            float t3 = acc[i][jg * 4 + 3] + bl[jg * 4 + 3];
            if (RES) {
                float4 r = *(const float4*)(R + rowoff + cb);
                t0 += r.x; t1 += r.y; t2 += r.z; t3 += r.w;
            }
            if (RELU) {
                t0 = fmaxf(t0, 0.f); t1 = fmaxf(t1, 0.f);
                t2 = fmaxf(t2, 0.f); t3 = fmaxf(t3, 0.f);
            }
            float4 v; v.x = t0; v.y = t1; v.z = t2; v.w = t3;
            *(float4*)(C + rowoff + cb) = v;
        }
    }
}

// ---------------- prefill flash attention (causal), 64x64 tiles ----------------
__global__ void __launch_bounds__(256) attn_prefill(const float* __restrict__ qkv,
                                                    float* __restrict__ attn)
{
    extern __shared__ float sm[];
    float* Qs = sm;
    float* KP = sm + 64 * 64;
    float* Vs = KP + 64 * 65;

    const int b  = blockIdx.y >> 3;
    const int h  = blockIdx.y & 7;
    const int l0 = blockIdx.x * 64;
    const int tid = threadIdx.x;
    const int tx = tid & 15, ty = tid >> 4;
    const int r0 = ty * 4, c0 = tx * 4;

    const size_t rowbase = (size_t)(b * S_) * 1536;
    const float* qbase = qkv + rowbase + h * 64;
    const float* kbase = qkv + rowbase + 512 + h * 64;
    const float* vbase = qkv + rowbase + 1024 + h * 64;

    const int lt  = tid >> 4;
    const int ld4 = (tid & 15) * 4;

#pragma unroll
    for (int tt = lt; tt < 64; tt += 16) {
        float4 q4 = *(const float4*)(qbase + (size_t)(l0 + tt) * 1536 + ld4);
        Qs[(ld4 + 0) * 64 + tt] = q4.x;
        Qs[(ld4 + 1) * 64 + tt] = q4.y;
        Qs[(ld4 + 2) * 64 + tt] = q4.z;
        Qs[(ld4 + 3) * 64 + tt] = q4.w;
    }

    float o[4][4];
    float mrow[4], lrow[4];
#pragma unroll
    for (int i = 0; i < 4; i++) {
        mrow[i] = -1e30f; lrow[i] = 0.f;
#pragma unroll
        for (int j = 0; j < 4; j++) o[i][j] = 0.f;
    }

    const int ntiles = (l0 >> 6) + 1;
    for (int tile = 0; tile < ntiles; ++tile) {
        const int j0 = tile * 64;
        __syncthreads();
#pragma unroll
        for (int tt = lt; tt < 64; tt += 16) {
            float4 k4 = *(const float4*)(kbase + (size_t)(j0 + tt) * 1536 + ld4);
            KP[(ld4 + 0) * 65 + tt] = k4.x;
            KP[(ld4 + 1) * 65 + tt] = k4.y;
            KP[(ld4 + 2) * 65 + tt] = k4.z;
            KP[(ld4 + 3) * 65 + tt] = k4.w;
            float4 v4 = *(const float4*)(vbase + (size_t)(j0 + tt) * 1536 + ld4);
            *(float4*)(Vs + tt * 64 + ld4) = v4;
        }
        __syncthreads();

        float s[4][4];
#pragma unroll
        for (int i = 0; i < 4; i++)
#pragma unroll
            for (int j = 0; j < 4; j++) s[i][j] = 0.f;

        for (int d = 0; d < 64; d++) {
            float qf[4];
            *(float4*)qf = *(const float4*)(Qs + d * 64 + r0);
            float kf0 = KP[d * 65 + c0 + 0];
            float kf1 = KP[d * 65 + c0 + 1];
            float kf2 = KP[d * 65 + c0 + 2];
            float kf3 = KP[d * 65 + c0 + 3];
#pragma unroll
            for (int i = 0; i < 4; i++) {
                s[i][0] = fmaf(qf[i], kf0, s[i][0]);
                s[i][1] = fmaf(qf[i], kf1, s[i][1]);
                s[i][2] = fmaf(qf[i], kf2, s[i][2]);
                s[i][3] = fmaf(qf[i], kf3, s[i][3]);
            }
        }

        if (j0 == l0) {
#pragma unroll
            for (int i = 0; i < 4; i++)
#pragma unroll
                for (int j = 0; j < 4; j++)
                    s[i][j] = (j0 + c0 + j > l0 + r0 + i) ? -1e30f : s[i][j] * 0.125f;
        } else {
#pragma unroll
            for (int i = 0; i < 4; i++)
#pragma unroll
                for (int j = 0; j < 4; j++) s[i][j] *= 0.125f;
        }

        float p[4][4];
#pragma unroll
        for (int i = 0; i < 4; i++) {
            float rm = fmaxf(fmaxf(s[i][0], s[i][1]), fmaxf(s[i][2], s[i][3]));
#pragma unroll
            for (int off = 8; off; off >>= 1)
                rm = fmaxf(rm, __shfl_xor_sync(0xffffffffu, rm, off));
            float mnew  = fmaxf(mrow[i], rm);
            float alpha = __expf(mrow[i] - mnew);
            float ps = 0.f;
#pragma unroll
            for (int j = 0; j < 4; j++) { p[i][j] = __expf(s[i][j] - mnew); ps += p[i][j]; }
#pragma unroll
            for (int off = 8; off; off >>= 1)
                ps += __shfl_xor_sync(0xffffffffu, ps, off);
            lrow[i] = lrow[i] * alpha + ps;
            mrow[i] = mnew;
#pragma unroll
            for (int j = 0; j < 4; j++) o[i][j] *= alpha;
        }

        __syncthreads();
#pragma unroll
        for (int i = 0; i < 4; i++)
#pragma unroll
            for (int j = 0; j < 4; j++)
                KP[(r0 + i) * 65 + c0 + j] = p[i][j];
        __syncthreads();

        for (int c = 0; c < 64; c++) {
            float vv[4];
            *(float4*)vv = *(const float4*)(Vs + c * 64 + c0);
            float p0 = KP[(r0 + 0) * 65 + c];
            float p1 = KP[(r0 + 1) * 65 + c];
            float p2 = KP[(r0 + 2) * 65 + c];
            float p3 = KP[(r0 + 3) * 65 + c];
#pragma unroll
            for (int j = 0; j < 4; j++) {
                o[0][j] = fmaf(p0, vv[j], o[0][j]);
                o[1][j] = fmaf(p1, vv[j], o[1][j]);
                o[2][j] = fmaf(p2, vv[j], o[2][j]);
                o[3][j] = fmaf(p3, vv[j], o[3][j]);
            }
        }
    }

    float* ob = attn + (size_t)(b * S_ + l0) * 512 + h * 64;
#pragma unroll
    for (int i = 0; i < 4; i++) {
        float inv = 1.f / lrow[i];
        float4 v;
        v.x = o[i][0] * inv; v.y = o[i][1] * inv;
        v.z = o[i][2] * inv; v.w = o[i][3] * inv;
        *(float4*)(ob + (size_t)(r0 + i) * 512 + c0) = v;
    }
}

// ---------------- copy prefill K/V slices into the caches ----------------
__global__ void __launch_bounds__(128) copy_kv(const float* __restrict__ qkv,
                                               float* __restrict__ kc, float* __restrict__ vc)
{
    const int r = blockIdx.x;
    const int b = r >> 10, s = r & 1023;
    const int tid = threadIdx.x;
    const float4* src = (const float4*)(qkv + (size_t)r * 1536);
    float4* kd = (float4*)(kc + (size_t)(b * CAP_ + s) * 512);
    float4* vd = (float4*)(vc + (size_t)(b * CAP_ + s) * 512);
    kd[tid] = src[128 + tid];
    vd[tid] = src[256 + tid];
}

// ---------------- prefill LayerNorm over rows of 512 ----------------
__global__ void __launch_bounds__(256) ln_rows(const float* __restrict__ in,
                                               const float* __restrict__ g,
                                               const float* __restrict__ be,
                                               float* __restrict__ out, int outExtra)
{
    const int r = blockIdx.x;
    const int tid = threadIdx.x;
    const float* row = in + (size_t)r * 512;
    float v0 = row[tid], v1 = row[tid + 256];
    float s  = warpRedSum(v0 + v1);
    float s2 = warpRedSum(v0 * v0 + v1 * v1);
    __shared__ float r1[8], r2[8];
    __shared__ float smu, srs;
    const int w = tid >> 5, lane = tid & 31;
    if (lane == 0) { r1[w] = s; r2[w] = s2; }
    __syncthreads();
    if (tid == 0) {
        float S = 0.f, S2 = 0.f;
#pragma unroll
        for (int i = 0; i < 8; i++) { S += r1[i]; S2 += r2[i]; }
        float mu  = S * (1.f / 512.f);
        float var = S2 * (1.f / 512.f) - mu * mu;
        smu = mu; srs = rsqrtf(var + 1e-5f);
    }
    __syncthreads();
    const int orow = r + (r >> 10) * outExtra;
    float* od = out + (size_t)orow * 512;
    od[tid]       = (v0 - smu) * srs * g[tid]       + be[tid];
    od[tid + 256] = (v1 - smu) * srs * g[tid + 256] + be[tid + 256];
}

// ---------------- megakernel building blocks ----------------
// 8-batch weight-stationary dot: one warp, one weight row, xs holds 8 rows [8][Ks]
template<int KP>
__device__ __forceinline__ void dot8(const float* __restrict__ wr,
                                     const float* xs, int Ks, int lane, float* acc)
{
#pragma unroll
    for (int b = 0; b < 8; b++) acc[b] = 0.f;
#pragma unroll 2
    for (int kp = 0; kp < KP; kp++) {
        const int k4 = kp * 128 + lane * 4;
        float4 wv = *(const float4*)(wr + k4);
#pragma unroll
        for (int b = 0; b < 8; b++) {
            float4 xv = *(const float4*)(xs + b * Ks + k4);
            acc[b] = fmaf(wv.x, xv.x, fmaf(wv.y, xv.y,
                     fmaf(wv.z, xv.z, fmaf(wv.w, xv.w, acc[b]))));
        }
    }
#pragma unroll
    for (int b = 0; b < 8; b++) acc[b] = warpRedSum(acc[b]);
}

// in-block residual + LayerNorm over one 512-row (256 threads)
__device__ __forceinline__ void block_ln(const float* __restrict__ a,
                                         const float* __restrict__ r,
                                         const float* __restrict__ gw,
                                         const float* __restrict__ gb,
                                         float* __restrict__ o,
                                         int tid, float* s_red)
{
    __syncthreads();
    float v0 = a[tid] + r[tid];
    float v1 = a[tid + 256] + r[tid + 256];
    float s  = warpRedSum(v0 + v1);
    float s2 = warpRedSum(v0 * v0 + v1 * v1);
    const int w = tid >> 5, lane = tid & 31;
    if (lane == 0) { s_red[w] = s; s_red[8 + w] = s2; }
    __syncthreads();
    float S = 0.f, S2 = 0.f;
#pragma unroll
    for (int i = 0; i < 8; i++) { S += s_red[i]; S2 += s_red[8 + i]; }
    float mu = S * (1.f / 512.f);
    float rs = rsqrtf(S2 * (1.f / 512.f) - mu * mu + 1e-5f);
    o[tid]       = (v0 - mu) * rs * gw[tid]       + gb[tid];
    o[tid + 256] = (v1 - mu) * rs * gw[tid + 256] + gb[tid + 256];
    __syncthreads();
}

// ---------------- decode megakernel: all 64 steps, n-split GEMVs ----------------
// grid: 128 blocks x 256 threads, dynamic smem = 64KB (xs)
__global__ void __launch_bounds__(256, 1) decode_mega(
    const float* __restrict__ dx,
    const float* __restrict__ qkvW, const float* __restrict__ qkvB,
    const float* __restrict__ outW, const float* __restrict__ outB,
    const float* __restrict__ w1, const float* __restrict__ b1,
    const float* __restrict__ w2, const float* __restrict__ b2,
    const float* __restrict__ ln1w, const float* __restrict__ ln1b,
    const float* __restrict__ ln2w, const float* __restrict__ ln2b,
    float* __restrict__ out,
    float* __restrict__ qt, float* __restrict__ kc, float* __restrict__ vc,
    float* __restrict__ hfft, float* __restrict__ t1,
    float* __restrict__ opart, float* __restrict__ mlpart)
{
    extern __shared__ float xs[];          // 16384 floats (64KB)
    __shared__ float s_ht[8 * 512];        // LN1 result, all 8 batches (16KB)
    __shared__ float s_red[32];
    __shared__ float s_q[64];
    __shared__ float s_part[256];
    __shared__ float s_comb[128];
    __shared__ unsigned s_base;

    const int tid  = threadIdx.x;
    const int bid  = blockIdx.x;
    const int w    = tid >> 5, lane = tid & 31;
    const int wg   = bid * 8 + w;          // 0..1023 global warp index

    if (tid == 0) s_base = g_flags[bid];   // flags persist across graph replays
    __syncthreads();
    unsigned target = s_base;

    float acc[8];

    for (int step = 0; step < STEPS_; step++) {
        const int cur = S_ + step;
        const float* xt = dx + (size_t)step * (B_ * D_);

        // ===== phase A: LN2 of previous step (blocks 0..7) + QKV GEMV =====
        if (step > 0 && bid < 8)
            block_ln(t1 + bid * 512, s_ht + bid * 512, ln2w, ln2b,
                     out + ((size_t)bid * CAP_ + (cur - 1)) * 512, tid, s_red);
        {
            const float4* src = (const float4*)xt;
            float4* dst = (float4*)xs;
            for (int i = tid; i < 1024; i += 256) dst[i] = src[i];
        }
        __syncthreads();
        // n1 = wg (q for wg<512, k otherwise)
        dot8<4>(qkvW + (size_t)wg * 512, xs, 512, lane, acc);
        if (lane == 0) {
            const float bv = qkvB[wg];
            if (wg < 512) {
#pragma unroll
                for (int b = 0; b < 8; b++) qt[b * 512 + wg] = acc[b] + bv;
            } else {
#pragma unroll
                for (int b = 0; b < 8; b++)
                    kc[((size_t)b * CAP_ + cur) * 512 + (wg - 512)] = acc[b] + bv;
            }
        }
        if (wg < 512) {  // n2 = wg + 1024 (v)
            dot8<4>(qkvW + (size_t)(wg + 1024) * 512, xs, 512, lane, acc);
            if (lane == 0) {
                const float bv = qkvB[wg + 1024];
#pragma unroll
                for (int b = 0; b < 8; b++)
                    vc[((size_t)b * CAP_ + cur) * 512 + wg] = acc[b] + bv;
            }
        }
        gbar(target, tid, bid);

        // ===== phase B: attention partials, all 128 blocks = (part, b, h) =====
        {
            const int part = bid >> 6;
            const int bb = (bid >> 3) & 7;
            const int h  = bid & 7;
            const int kvlen = cur + 1;
            const int hlen  = kvlen >> 1;
            const int tstart = part ? hlen : 0;
            const int tend   = part ? kvlen : hlen;
            if (tid < 64) s_q[tid] = qt[bb * 512 + h * 64 + tid];
            __syncthreads();
            const int tl = lane >> 2;
            const int kq = (lane & 3) * 16;
            const float4 qa = *(const float4*)(s_q + kq);
            const float4 qb = *(const float4*)(s_q + kq + 4);
            const float4 qc = *(const float4*)(s_q + kq + 8);
            const float4 qd = *(const float4*)(s_q + kq + 12);
            const float* kb = kc + (size_t)bb * CAP_ * 512 + h * 64;
            for (int t0 = tstart; t0 < tend; t0 += 64) {
                const int t = t0 + w * 8 + tl;
                const bool valid = t < tend;
                const float* kr = kb + (size_t)(valid ? t : tstart) * 512 + kq;
                float4 k0 = *(const float4*)(kr);
                float4 k1 = *(const float4*)(kr + 4);
                float4 k2 = *(const float4*)(kr + 8);
                float4 k3 = *(const float4*)(kr + 12);
                float s;
                s = k0.x * qa.x;
                s = fmaf(k0.y, qa.y, s); s = fmaf(k0.z, qa.z, s); s = fmaf(k0.w, qa.w, s);
                s = fmaf(k1.x, qb.x, s); s = fmaf(k1.y, qb.y, s);
                s = fmaf(k1.z, qb.z, s); s = fmaf(k1.w, qb.w, s);
                s = fmaf(k2.x, qc.x, s); s = fmaf(k2.y, qc.y, s);
                s = fmaf(k2.z, qc.z, s); s = fmaf(k2.w, qc.w, s);
                s = fmaf(k3.x, qd.x, s); s = fmaf(k3.y, qd.y, s);
                s = fmaf(k3.z, qd.z, s); s = fmaf(k3.w, qd.w, s);
                s += __shfl_xor_sync(0xffffffffu, s, 1);
                s += __shfl_xor_sync(0xffffffffu, s, 2);
                if (valid && (lane & 3) == 0) xs[t] = s * 0.125f;
            }
            __syncthreads();
            float lmax = -1e30f;
            for (int t = tstart + tid; t < tend; t += 256) lmax = fmaxf(lmax, xs[t]);
            lmax = warpRedMax(lmax);
            if (lane == 0) s_red[w] = lmax;
            __syncthreads();
            float gm = s_red[0];
#pragma unroll
            for (int i = 1; i < 8; i++) gm = fmaxf(gm, s_red[i]);
            float ls = 0.f;
            for (int t = tstart + tid; t < tend; t += 256) {
                float p = __expf(xs[t] - gm);
                xs[t] = p;
                ls += p;
            }
            ls = warpRedSum(ls);
            if (lane == 0) s_red[8 + w] = ls;
            __syncthreads();
            float ssum = 0.f;
#pragma unroll
            for (int i = 0; i < 8; i++) ssum += s_red[8 + i];
            const int d = tid & 63, pt = tid >> 6;
            const float* vb = vc + (size_t)bb * CAP_ * 512 + h * 64 + d;
            float vacc = 0.f;
            for (int t = tstart + pt; t < tend; t += 4)
                vacc = fmaf(xs[t], vb[(size_t)t * 512], vacc);
            s_part[tid] = vacc;
            __syncthreads();
            const int gi = part * 64 + bb * 8 + h;
            if (pt == 0)
                opart[gi * 64 + d] =
                    s_part[d] + s_part[64 + d] + s_part[128 + d] + s_part[192 + d];
            if (tid == 0) { mlpart[gi * 2] = gm; mlpart[gi * 2 + 1] = ssum; }
        }
        gbar(target, tid, bid);

        // ===== phase C: combine attention parts into xs, out-projection =====
        if (tid < 64) {
            float m1 = mlpart[tid * 2],        l1 = mlpart[tid * 2 + 1];
            float m2 = mlpart[(64 + tid) * 2], l2 = mlpart[(64 + tid) * 2 + 1];
            float gm = fmaxf(m1, m2);
            float e1 = __expf(m1 - gm), e2 = __expf(m2 - gm);
            float inv = 1.f / (e1 * l1 + e2 * l2);
            s_comb[tid * 2]     = e1 * inv;
            s_comb[tid * 2 + 1] = e2 * inv;
        }
        __syncthreads();
        for (int i = tid; i < 4096; i += 256) {
            const int idx = i >> 6;   // b*8 + h
            const int d = i & 63;
            xs[i] = s_comb[idx * 2]     * opart[idx * 64 + d]
                  + s_comb[idx * 2 + 1] * opart[(64 + idx) * 64 + d];
        }
        __syncthreads();
        if (wg < 512) {
            dot8<4>(outW + (size_t)wg * 512, xs, 512, lane, acc);
            if (lane == 0) {
                const float bv = outB[wg];
#pragma unroll
                for (int b = 0; b < 8; b++) t1[b * 512 + wg] = acc[b] + bv;
            }
        }
        gbar(target, tid, bid);

        // ===== phase E: LN1 (per-warp, redundant per block) + FF1 =====
        {
            const float* trow = t1 + w * 512;
            const float* xrow = xt + w * 512;
            float vals[16];
            float sv = 0.f, sq = 0.f;
#pragma unroll
            for (int gld = 0; gld < 4; gld++) {
                float4 tv = *(const float4*)(trow + gld * 128 + lane * 4);
                float4 xv = *(const float4*)(xrow + gld * 128 + lane * 4);
                float a0 = tv.x + xv.x, a1 = tv.y + xv.y;
                float a2 = tv.z + xv.z, a3 = tv.w + xv.w;
                vals[gld * 4 + 0] = a0; vals[gld * 4 + 1] = a1;
                vals[gld * 4 + 2] = a2; vals[gld * 4 + 3] = a3;
                sv += a0 + a1 + a2 + a3;
                sq += a0 * a0 + a1 * a1 + a2 * a2 + a3 * a3;
            }
            sv = warpRedSum(sv); sq = warpRedSum(sq);
            float mu = sv * (1.f / 512.f);
            float rs = rsqrtf(sq * (1.f / 512.f) - mu * mu + 1e-5f);
#pragma unroll
            for (int gld = 0; gld < 4; gld++)
#pragma unroll
                for (int j = 0; j < 4; j++) {
                    const int idx = gld * 128 + lane * 4 + j;
                    s_ht[w * 512 + idx] =
                        (vals[gld * 4 + j] - mu) * rs * ln1w[idx] + ln1b[idx];
                }
        }
        __syncthreads();
        dot8<4>(w1 + (size_t)wg * 512, s_ht, 512, lane, acc);
        if (lane == 0) {
            const float bv = b1[wg];
#pragma unroll
            for (int b = 0; b < 8; b++)
                hfft[b * 2048 + wg] = fmaxf(acc[b] + bv, 0.f);
        }
        dot8<4>(w1 + (size_t)(wg + 1024) * 512, s_ht, 512, lane, acc);
        if (lane == 0) {
            const float bv = b1[wg + 1024];
#pragma unroll
            for (int b = 0; b < 8; b++)
                hfft[b * 2048 + wg + 1024] = fmaxf(acc[b] + bv, 0.f);
        }
        gbar(target, tid, bid);

        // ===== phase F: FF2 (K=2048) =====
        {
            const float4* src = (const float4*)hfft;
            float4* dst = (float4*)xs;
            for (int i = tid; i < 4096; i += 256) dst[i] = src[i];
        }
        __syncthreads();
        if (wg < 512) {
            dot8<16>(w2 + (size_t)wg * 2048, xs, 2048, lane, acc);
            if (lane == 0) {
                const float bv = b2[wg];
#pragma unroll
                for (int b = 0; b < 8; b++) t1[b * 512 + wg] = acc[b] + bv;
            }
        }
        gbar(target, tid, bid);
    }

    // final LN2 for the last step
    if (bid < 8)
        block_ln(t1 + bid * 512, s_ht + bid * 512, ln2w, ln2b,
                 out + ((size_t)bid * CAP_ + (S_ + STEPS_ - 1)) * 512, tid, s_red);
}

// ---------------- host launcher ----------------
struct ScratchPtrs {
    float *Qkv, *Attn, *Pre, *Hb, *Hff, *Kc, *Vc, *Qt, *Hfft, *T1, *Op, *Ml;
};

static const ScratchPtrs& get_scratch() {
    static ScratchPtrs p;
    static bool init = false;
    if (!init) {
        cudaGetSymbolAddress((void**)&p.Qkv,  g_qkv);
        cudaGetSymbolAddress((void**)&p.Attn, g_attn);
        cudaGetSymbolAddress((void**)&p.Pre,  g_pre);
        cudaGetSymbolAddress((void**)&p.Hb,   g_h);
        cudaGetSymbolAddress((void**)&p.Hff,  g_hff);
        cudaGetSymbolAddress((void**)&p.Kc,   g_kc);
        cudaGetSymbolAddress((void**)&p.Vc,   g_vc);
        cudaGetSymbolAddress((void**)&p.Qt,   g_qt);
        cudaGetSymbolAddress((void**)&p.Hfft, g_hfft);
        cudaGetSymbolAddress((void**)&p.T1,   g_t1);
        cudaGetSymbolAddress((void**)&p.Op,   g_op);
        cudaGetSymbolAddress((void**)&p.Ml,   g_ml);
        cudaFuncSetAttribute(attn_prefill,
                             cudaFuncAttributeMaxDynamicSharedMemorySize, 49408);
        cudaFuncSetAttribute(decode_mega,
                             cudaFuncAttributeMaxDynamicSharedMemorySize, 65536);
        init = true;
    }
    return p;
}

extern "C" void kernel_launch(void* const* d_in, const int* in_sizes, int n_in,
                              void* d_out, int out_size)
{
    (void)in_sizes; (void)n_in; (void)out_size;
    const float* x    = (const float*)d_in[0];
    const float* dx   = (const float*)d_in[1];
    // d_in[2] = causal_mask (bool) — unused, causality computed analytically
    const float* qkvW = (const float*)d_in[3];
    const float* qkvB = (const float*)d_in[4];
    const float* outW = (const float*)d_in[5];
    const float* outB = (const float*)d_in[6];
    const float* w1   = (const float*)d_in[7];
    const float* b1   = (const float*)d_in[8];
    const float* w2   = (const float*)d_in[9];
    const float* b2   = (const float*)d_in[10];
    const float* ln1w = (const float*)d_in[11];
    const float* ln1b = (const float*)d_in[12];
    const float* ln2w = (const float*)d_in[13];
    const float* ln2b = (const float*)d_in[14];
    float* out = (float*)d_out;

    const ScratchPtrs& sp = get_scratch();

    // ---- prefill ----
    sgemm_nt<1,0,0><<<dim3(12, 64), 256>>>(x, qkvW, qkvB, nullptr, sp.Qkv, MTOK, 1536, 512);
    copy_kv<<<MTOK, 128>>>(sp.Qkv, sp.Kc, sp.Vc);
    attn_prefill<<<dim3(16, 64), 256, 49408>>>(sp.Qkv, sp.Attn);
    sgemm_nt<1,0,1><<<dim3(4, 64), 256>>>(sp.Attn, outW, outB, x, sp.Pre, MTOK, 512, 512);
    ln_rows<<<MTOK, 256>>>(sp.Pre, ln1w, ln1b, sp.Hb, 0);
    sgemm_nt<1,1,0><<<dim3(16, 64), 256>>>(sp.Hb, w1, b1, nullptr, sp.Hff, MTOK, 2048, 512);
    sgemm_nt<1,0,1><<<dim3(4, 64), 256>>>(sp.Hff, w2, b2, sp.Hb, sp.Pre, MTOK, 512, 2048);
    ln_rows<<<MTOK, 256>>>(sp.Pre, ln2w, ln2b, out, 64);

    // ---- decode: all 64 steps in one persistent launch ----
    decode_mega<<<NBLK, 256, 65536>>>(dx, qkvW, qkvB, outW, outB,
                                      w1, b1, w2, b2,
                                      ln1w, ln1b, ln2w, ln2b, out,
                                      sp.Qt, sp.Kc, sp.Vc,
                                      sp.Hfft, sp.T1, sp.Op, sp.Ml);
}

// round 4
// speedup vs baseline: 1.4779x; 1.4779x over previous
#include <cuda_runtime.h>
#include <cstdint>

#define B_     8
#define S_     1024
#define D_     512
#define H_     8
#define HD_    64
#define FF_    2048
#define STEPS_ 64
#define CAP_   1088
#define MTOK   (B_*S_)   /* 8192 */
#define NBLK   128

// ---------------- device scratch (no cudaMalloc allowed) ----------------
__device__ float g_qkv [MTOK*1536];   // prefill QKV
__device__ float g_attn[MTOK*D_];     // prefill attention output
__device__ float g_pre [MTOK*D_];     // pre-LN buffer
__device__ float g_h   [MTOK*D_];     // post-LN1 hidden
__device__ float g_hff [MTOK*FF_];    // MLP hidden
__device__ float g_kc  [B_*CAP_*D_];  // K cache
__device__ float g_vc  [B_*CAP_*D_];  // V cache
__device__ float g_qt  [B_*D_];       // decode q
__device__ float g_at  [B_*D_];       // decode attn out
__device__ float g_hfft[B_*FF_];      // decode MLP hidden
__device__ float g_t1  [B_*D_];       // decode temp
__device__ unsigned g_bar_count;      // central barrier arrivals
__device__ unsigned g_bar_sense;      // central barrier release sense

// ---------------- reductions ----------------
__device__ __forceinline__ float warpRedSum(float v) {
#pragma unroll
    for (int o = 16; o; o >>= 1) v += __shfl_xor_sync(0xffffffffu, v, o);
    return v;
}
__device__ __forceinline__ float warpRedMax(float v) {
#pragma unroll
    for (int o = 16; o; o >>= 1) v = fmaxf(v, __shfl_xor_sync(0xffffffffu, v, o));
    return v;
}

// ---------------- central barrier, load-based poll ----------------
__device__ __forceinline__ unsigned ld_acq(const unsigned* p) {
    unsigned v;
    asm volatile("ld.acquire.gpu.u32 %0, [%1];" : "=r"(v) : "l"(p) : "memory");
    return v;
}
__device__ __forceinline__ void st_rel(unsigned* p, unsigned v) {
    asm volatile("st.release.gpu.u32 [%0], %1;" :: "l"(p), "r"(v) : "memory");
}
__device__ __forceinline__ void gbar(unsigned& target, int tid) {
    __threadfence();               // make this thread's writes visible gpu-wide
    __syncthreads();               // all threads of block done + visible
    target += 1;
    if (tid == 0) {
        unsigned a = atomicAdd(&g_bar_count, 1u) + 1u;
        if (a == (unsigned)NBLK) {
            atomicExch(&g_bar_count, 0u);
            st_rel(&g_bar_sense, target);
        } else {
            while ((int)(ld_acq(&g_bar_sense) - target) < 0) { }
        }
    }
    __syncthreads();
    __threadfence();               // invalidate L1 so fresh peer data is seen
}

// ---------------- SGEMM (NT): C[m,n] = sum_k A[m,k]*B[n,k] (+bias,+res,relu) ----------------
// BM=BN=128, BK=16, 256 threads, 2 blocks/SM; 4+4 split tile for conflict-free LDS.128
template<int BIAS, int RELU, int RES>
__global__ void __launch_bounds__(256, 2) sgemm_nt(
    const float* __restrict__ A, const float* __restrict__ Bm,
    const float* __restrict__ bias, const float* __restrict__ R,
    float* __restrict__ C, int M, int N, int K)
{
    __shared__ float As[16][132];
    __shared__ float Bs[16][132];
    const int tid = threadIdx.x;
    const int m0 = blockIdx.y * 128;
    const int n0 = blockIdx.x * 128;
    const int tx = tid & 15, ty = tid >> 4;
    const int r0 = ty * 4, c0 = tx * 4;
    const int lrow = tid >> 2;
    const int lk4  = (tid & 3) * 4;

    float acc[8][8];
#pragma unroll
    for (int i = 0; i < 8; i++)
#pragma unroll
        for (int j = 0; j < 8; j++) acc[i][j] = 0.f;

    for (int k0 = 0; k0 < K; k0 += 16) {
#pragma unroll
        for (int half = 0; half < 2; half++) {
            int row = lrow + half * 64;
            float4 a = *(const float4*)(A + (size_t)(m0 + row) * K + k0 + lk4);
            As[lk4 + 0][row] = a.x; As[lk4 + 1][row] = a.y;
            As[lk4 + 2][row] = a.z; As[lk4 + 3][row] = a.w;
            float4 b = *(const float4*)(Bm + (size_t)(n0 + row) * K + k0 + lk4);
            Bs[lk4 + 0][row] = b.x; Bs[lk4 + 1][row] = b.y;
            Bs[lk4 + 2][row] = b.z; Bs[lk4 + 3][row] = b.w;
        }
        __syncthreads();
#pragma unroll
        for (int kk = 0; kk < 16; kk++) {
            float af[8], bf[8];
            *(float4*)(af)     = *(const float4*)(&As[kk][r0]);
            *(float4*)(af + 4) = *(const float4*)(&As[kk][r0 + 64]);
            *(float4*)(bf)     = *(const float4*)(&Bs[kk][c0]);
            *(float4*)(bf + 4) = *(const float4*)(&Bs[kk][c0 + 64]);
#pragma unroll
            for (int i = 0; i < 8; i++)
#pragma unroll
                for (int j = 0; j < 8; j++)
                    acc[i][j] = fmaf(af[i], bf[j], acc[i][j]);
        }
        __syncthreads();
    }

    float bl[8];
#pragma unroll
    for (int j = 0; j < 8; j++)
        bl[j] = BIAS ? bias[n0 + c0 + (j < 4 ? j : 60 + j)] : 0.f;

#pragma unroll
    for (int i = 0; i < 8; i++) {
        const int row = m0 + r0 + (i < 4 ? i : 60 + i);
        const size_t rowoff = (size_t)row * N + n0;
#pragma unroll
        for (int jg = 0; jg < 2; jg++) {
            const int cb = c0 + jg * 64;
            float t0 = acc[i][jg * 4 + 0] + bl[jg * 4 + 0];
            float t1 = acc[i][jg * 4 + 1] + bl[jg * 4 + 1];
            float t2 = acc[i][jg * 4 + 2] + bl[jg * 4 + 2];
            float t3 = acc[i][jg * 4 + 3] + bl[jg * 4 + 3];
            if (RES) {
                float4 r = *(const float4*)(R + rowoff + cb);
                t0 += r.x; t1 += r.y; t2 += r.z; t3 += r.w;
            }
            if (RELU) {
                t0 = fmaxf(t0, 0.f); t1 = fmaxf(t1, 0.f);
                t2 = fmaxf(t2, 0.f); t3 = fmaxf(t3, 0.f);
            }
            float4 v; v.x = t0; v.y = t1; v.z = t2; v.w = t3;
            *(float4*)(C + rowoff + cb) = v;
        }
    }
}

// ---------------- prefill flash attention (causal), 64x64 tiles ----------------
__global__ void __launch_bounds__(256) attn_prefill(const float* __restrict__ qkv,
                                                    float* __restrict__ attn)
{
    extern __shared__ float sm[];
    float* Qs = sm;
    float* KP = sm + 64 * 64;
    float* Vs = KP + 64 * 65;

    const int b  = blockIdx.y >> 3;
    const int h  = blockIdx.y & 7;
    const int l0 = blockIdx.x * 64;
    const int tid = threadIdx.x;
    const int tx = tid & 15, ty = tid >> 4;
    const int r0 = ty * 4, c0 = tx * 4;

    const size_t rowbase = (size_t)(b * S_) * 1536;
    const float* qbase = qkv + rowbase + h * 64;
    const float* kbase = qkv + rowbase + 512 + h * 64;
    const float* vbase = qkv + rowbase + 1024 + h * 64;

    const int lt  = tid >> 4;
    const int ld4 = (tid & 15) * 4;

#pragma unroll
    for (int tt = lt; tt < 64; tt += 16) {
        float4 q4 = *(const float4*)(qbase + (size_t)(l0 + tt) * 1536 + ld4);
        Qs[(ld4 + 0) * 64 + tt] = q4.x;
        Qs[(ld4 + 1) * 64 + tt] = q4.y;
        Qs[(ld4 + 2) * 64 + tt] = q4.z;
        Qs[(ld4 + 3) * 64 + tt] = q4.w;
    }

    float o[4][4];
    float mrow[4], lrow[4];
#pragma unroll
    for (int i = 0; i < 4; i++) {
        mrow[i] = -1e30f; lrow[i] = 0.f;
#pragma unroll
        for (int j = 0; j < 4; j++) o[i][j] = 0.f;
    }

    const int ntiles = (l0 >> 6) + 1;
    for (int tile = 0; tile < ntiles; ++tile) {
        const int j0 = tile * 64;
        __syncthreads();
#pragma unroll
        for (int tt = lt; tt < 64; tt += 16) {
            float4 k4 = *(const float4*)(kbase + (size_t)(j0 + tt) * 1536 + ld4);
            KP[(ld4 + 0) * 65 + tt] = k4.x;
            KP[(ld4 + 1) * 65 + tt] = k4.y;
            KP[(ld4 + 2) * 65 + tt] = k4.z;
            KP[(ld4 + 3) * 65 + tt] = k4.w;
            float4 v4 = *(const float4*)(vbase + (size_t)(j0 + tt) * 1536 + ld4);
            *(float4*)(Vs + tt * 64 + ld4) = v4;
        }
        __syncthreads();

        float s[4][4];
#pragma unroll
        for (int i = 0; i < 4; i++)
#pragma unroll
            for (int j = 0; j < 4; j++) s[i][j] = 0.f;

        for (int d = 0; d < 64; d++) {
            float qf[4];
            *(float4*)qf = *(const float4*)(Qs + d * 64 + r0);
            float kf0 = KP[d * 65 + c0 + 0];
            float kf1 = KP[d * 65 + c0 + 1];
            float kf2 = KP[d * 65 + c0 + 2];
            float kf3 = KP[d * 65 + c0 + 3];
#pragma unroll
            for (int i = 0; i < 4; i++) {
                s[i][0] = fmaf(qf[i], kf0, s[i][0]);
                s[i][1] = fmaf(qf[i], kf1, s[i][1]);
                s[i][2] = fmaf(qf[i], kf2, s[i][2]);
                s[i][3] = fmaf(qf[i], kf3, s[i][3]);
            }
        }

        if (j0 == l0) {
#pragma unroll
            for (int i = 0; i < 4; i++)
#pragma unroll
                for (int j = 0; j < 4; j++)
                    s[i][j] = (j0 + c0 + j > l0 + r0 + i) ? -1e30f : s[i][j] * 0.125f;
        } else {
#pragma unroll
            for (int i = 0; i < 4; i++)
#pragma unroll
                for (int j = 0; j < 4; j++) s[i][j] *= 0.125f;
        }

        float p[4][4];
#pragma unroll
        for (int i = 0; i < 4; i++) {
            float rm = fmaxf(fmaxf(s[i][0], s[i][1]), fmaxf(s[i][2], s[i][3]));
#pragma unroll
            for (int off = 8; off; off >>= 1)
                rm = fmaxf(rm, __shfl_xor_sync(0xffffffffu, rm, off));
            float mnew  = fmaxf(mrow[i], rm);
            float alpha = __expf(mrow[i] - mnew);
            float ps = 0.f;
#pragma unroll
            for (int j = 0; j < 4; j++) { p[i][j] = __expf(s[i][j] - mnew); ps += p[i][j]; }
#pragma unroll
            for (int off = 8; off; off >>= 1)
                ps += __shfl_xor_sync(0xffffffffu, ps, off);
            lrow[i] = lrow[i] * alpha + ps;
            mrow[i] = mnew;
#pragma unroll
            for (int j = 0; j < 4; j++) o[i][j] *= alpha;
        }

        __syncthreads();
#pragma unroll
        for (int i = 0; i < 4; i++)
#pragma unroll
            for (int j = 0; j < 4; j++)
                KP[(r0 + i) * 65 + c0 + j] = p[i][j];
        __syncthreads();

        for (int c = 0; c < 64; c++) {
            float vv[4];
            *(float4*)vv = *(const float4*)(Vs + c * 64 + c0);
            float p0 = KP[(r0 + 0) * 65 + c];
            float p1 = KP[(r0 + 1) * 65 + c];
            float p2 = KP[(r0 + 2) * 65 + c];
            float p3 = KP[(r0 + 3) * 65 + c];
#pragma unroll
            for (int j = 0; j < 4; j++) {
                o[0][j] = fmaf(p0, vv[j], o[0][j]);
                o[1][j] = fmaf(p1, vv[j], o[1][j]);
                o[2][j] = fmaf(p2, vv[j], o[2][j]);
                o[3][j] = fmaf(p3, vv[j], o[3][j]);
            }
        }
    }

    float* ob = attn + (size_t)(b * S_ + l0) * 512 + h * 64;
#pragma unroll
    for (int i = 0; i < 4; i++) {
        float inv = 1.f / lrow[i];
        float4 v;
        v.x = o[i][0] * inv; v.y = o[i][1] * inv;
        v.z = o[i][2] * inv; v.w = o[i][3] * inv;
        *(float4*)(ob + (size_t)(r0 + i) * 512 + c0) = v;
    }
}

// ---------------- copy prefill K/V slices into the caches ----------------
__global__ void __launch_bounds__(128) copy_kv(const float* __restrict__ qkv,
                                               float* __restrict__ kc, float* __restrict__ vc)
{
    const int r = blockIdx.x;
    const int b = r >> 10, s = r & 1023;
    const int tid = threadIdx.x;
    const float4* src = (const float4*)(qkv + (size_t)r * 1536);
    float4* kd = (float4*)(kc + (size_t)(b * CAP_ + s) * 512);
    float4* vd = (float4*)(vc + (size_t)(b * CAP_ + s) * 512);
    kd[tid] = src[128 + tid];
    vd[tid] = src[256 + tid];
}

// ---------------- prefill LayerNorm over rows of 512 ----------------
__global__ void __launch_bounds__(256) ln_rows(const float* __restrict__ in,
                                               const float* __restrict__ g,
                                               const float* __restrict__ be,
                                               float* __restrict__ out, int outExtra)
{
    const int r = blockIdx.x;
    const int tid = threadIdx.x;
    const float* row = in + (size_t)r * 512;
    float v0 = row[tid], v1 = row[tid + 256];
    float s  = warpRedSum(v0 + v1);
    float s2 = warpRedSum(v0 * v0 + v1 * v1);
    __shared__ float r1[8], r2[8];
    __shared__ float smu, srs;
    const int w = tid >> 5, lane = tid & 31;
    if (lane == 0) { r1[w] = s; r2[w] = s2; }
    __syncthreads();
    if (tid == 0) {
        float S = 0.f, S2 = 0.f;
#pragma unroll
        for (int i = 0; i < 8; i++) { S += r1[i]; S2 += r2[i]; }
        float mu  = S * (1.f / 512.f);
        float var = S2 * (1.f / 512.f) - mu * mu;
        smu = mu; srs = rsqrtf(var + 1e-5f);
    }
    __syncthreads();
    const int orow = r + (r >> 10) * outExtra;
    float* od = out + (size_t)orow * 512;
    od[tid]       = (v0 - smu) * srs * g[tid]       + be[tid];
    od[tid + 256] = (v1 - smu) * srs * g[tid + 256] + be[tid + 256];
}

// ---------------- megakernel building blocks ----------------
// 4-batch weight-stationary dot: one warp, one weight row, xs holds 4 rows [4][Kstride]
template<int KP>
__device__ __forceinline__ void dot4(const float* __restrict__ wr,
                                     const float* xs, int Kstride, int lane,
                                     float& a0, float& a1, float& a2, float& a3)
{
    a0 = a1 = a2 = a3 = 0.f;
#pragma unroll
    for (int kp = 0; kp < KP; kp++) {
        const int k4 = kp * 128 + lane * 4;
        float4 wv = *(const float4*)(wr + k4);
        float4 x0 = *(const float4*)(xs + k4);
        float4 x1 = *(const float4*)(xs + Kstride + k4);
        float4 x2 = *(const float4*)(xs + 2 * Kstride + k4);
        float4 x3 = *(const float4*)(xs + 3 * Kstride + k4);
        a0 = fmaf(wv.x, x0.x, fmaf(wv.y, x0.y, fmaf(wv.z, x0.z, fmaf(wv.w, x0.w, a0))));
        a1 = fmaf(wv.x, x1.x, fmaf(wv.y, x1.y, fmaf(wv.z, x1.z, fmaf(wv.w, x1.w, a1))));
        a2 = fmaf(wv.x, x2.x, fmaf(wv.y, x2.y, fmaf(wv.z, x2.z, fmaf(wv.w, x2.w, a2))));
        a3 = fmaf(wv.x, x3.x, fmaf(wv.y, x3.y, fmaf(wv.z, x3.z, fmaf(wv.w, x3.w, a3))));
    }
    a0 = warpRedSum(a0); a1 = warpRedSum(a1);
    a2 = warpRedSum(a2); a3 = warpRedSum(a3);
}

// per-warp LayerNorm of one 512-row: val = a[i] + r[i]; out may be smem or global
__device__ __forceinline__ void warp_ln(const float* __restrict__ a,
                                        const float* __restrict__ r,
                                        const float* __restrict__ gw,
                                        const float* __restrict__ gb,
                                        float* __restrict__ o, int lane)
{
    float vals[16];
    float sv = 0.f, sq = 0.f;
#pragma unroll
    for (int g = 0; g < 4; g++) {
        const int idx = g * 128 + lane * 4;
        float4 av = *(const float4*)(a + idx);
        float4 rv = *(const float4*)(r + idx);
        float a0 = av.x + rv.x, a1 = av.y + rv.y;
        float a2 = av.z + rv.z, a3 = av.w + rv.w;
        vals[g * 4 + 0] = a0; vals[g * 4 + 1] = a1;
        vals[g * 4 + 2] = a2; vals[g * 4 + 3] = a3;
        sv += a0 + a1 + a2 + a3;
        sq += a0 * a0 + a1 * a1 + a2 * a2 + a3 * a3;
    }
    sv = warpRedSum(sv); sq = warpRedSum(sq);
    float mu = sv * (1.f / 512.f);
    float rs = rsqrtf(sq * (1.f / 512.f) - mu * mu + 1e-5f);
#pragma unroll
    for (int g = 0; g < 4; g++)
#pragma unroll
        for (int j = 0; j < 4; j++) {
            const int idx = g * 128 + lane * 4 + j;
            o[idx] = (vals[g * 4 + j] - mu) * rs * gw[idx] + gb[idx];
        }
}

// ---------------- decode megakernel: all 64 steps in one launch ----------------
// grid: 128 blocks x 256 threads, dynamic smem = 32KB
__global__ void __launch_bounds__(256, 1) decode_mega(
    const float* __restrict__ dx,
    const float* __restrict__ qkvW, const float* __restrict__ qkvB,
    const float* __restrict__ outW, const float* __restrict__ outB,
    const float* __restrict__ w1, const float* __restrict__ b1,
    const float* __restrict__ w2, const float* __restrict__ b2,
    const float* __restrict__ ln1w, const float* __restrict__ ln1b,
    const float* __restrict__ ln2w, const float* __restrict__ ln2b,
    float* __restrict__ out,
    float* __restrict__ qt, float* __restrict__ kc, float* __restrict__ vc,
    float* __restrict__ at, float* __restrict__ hfft, float* __restrict__ t1)
{
    extern __shared__ float xs[];      // 8192 floats (32KB)
    __shared__ float s_ln[4 * 512];    // LN1 rows b0..b0+3 (8KB) — persists to next step
    __shared__ float s_red[16];
    __shared__ float s_q[64];
    __shared__ float s_part[256];
    __shared__ unsigned s_base;

    const int tid  = threadIdx.x;
    const int bid  = blockIdx.x;
    const int w    = tid >> 5, lane = tid & 31;
    const int half = bid >> 6;           // 0/1: 4-batch group
    const int b0   = half * 4;
    const int wg   = (bid & 63) * 8 + w; // 0..511

    if (tid == 0) s_base = ld_acq(&g_bar_sense);  // sense persists across replays
    __syncthreads();
    unsigned target = s_base;

    for (int step = 0; step < STEPS_; step++) {
        const int cur = S_ + step;
        const float* xt = dx + (size_t)step * (B_ * D_);

        // ===== phase A: LN2(prev) on blocks 0 & 64 (4 rows each, from s_ln) + QKV =====
        if (step > 0 && (bid == 0 || bid == 64) && w < 4)
            warp_ln(t1 + (b0 + w) * 512, s_ln + w * 512, ln2w, ln2b,
                    out + ((size_t)(b0 + w) * CAP_ + (cur - 1)) * 512, lane);
        {
            const float4* src = (const float4*)(xt + b0 * 512);
            float4* dst = (float4*)xs;
            for (int i = tid; i < 512; i += 256) dst[i] = src[i];
        }
        __syncthreads();
#pragma unroll
        for (int o = 0; o < 3; o++) {
            const int n = wg + o * 512;
            float a0, a1, a2, a3;
            dot4<4>(qkvW + (size_t)n * 512, xs, 512, lane, a0, a1, a2, a3);
            if (lane == 0) {
                const float bv = qkvB[n];
                if (o == 0) {
                    qt[(b0 + 0) * 512 + wg] = a0 + bv;
                    qt[(b0 + 1) * 512 + wg] = a1 + bv;
                    qt[(b0 + 2) * 512 + wg] = a2 + bv;
                    qt[(b0 + 3) * 512 + wg] = a3 + bv;
                } else if (o == 1) {
                    kc[((size_t)(b0 + 0) * CAP_ + cur) * 512 + wg] = a0 + bv;
                    kc[((size_t)(b0 + 1) * CAP_ + cur) * 512 + wg] = a1 + bv;
                    kc[((size_t)(b0 + 2) * CAP_ + cur) * 512 + wg] = a2 + bv;
                    kc[((size_t)(b0 + 3) * CAP_ + cur) * 512 + wg] = a3 + bv;
                } else {
                    vc[((size_t)(b0 + 0) * CAP_ + cur) * 512 + wg] = a0 + bv;
                    vc[((size_t)(b0 + 1) * CAP_ + cur) * 512 + wg] = a1 + bv;
                    vc[((size_t)(b0 + 2) * CAP_ + cur) * 512 + wg] = a2 + bv;
                    vc[((size_t)(b0 + 3) * CAP_ + cur) * 512 + wg] = a3 + bv;
                }
            }
        }
        gbar(target, tid);

        // ===== phase B: attention, blocks 0..63 = (b, h) =====
        if (bid < 64) {
            const int h = bid & 7, bb = bid >> 3;
            const int kvlen = cur + 1;
            if (tid < 64) s_q[tid] = qt[bb * 512 + h * 64 + tid];
            __syncthreads();
            const int tl = lane >> 2;
            const int kq = (lane & 3) * 16;
            const float4 qa = *(const float4*)(s_q + kq);
            const float4 qb = *(const float4*)(s_q + kq + 4);
            const float4 qc = *(const float4*)(s_q + kq + 8);
            const float4 qd = *(const float4*)(s_q + kq + 12);
            const float* kb = kc + (size_t)bb * CAP_ * 512 + h * 64;
            for (int t0 = 0; t0 < kvlen; t0 += 64) {
                const int t = t0 + w * 8 + tl;
                const bool valid = t < kvlen;
                const float* kr = kb + (size_t)(valid ? t : 0) * 512 + kq;
                float4 k0 = *(const float4*)(kr);
                float4 k1 = *(const float4*)(kr + 4);
                float4 k2 = *(const float4*)(kr + 8);
                float4 k3 = *(const float4*)(kr + 12);
                float s;
                s = k0.x * qa.x;
                s = fmaf(k0.y, qa.y, s); s = fmaf(k0.z, qa.z, s); s = fmaf(k0.w, qa.w, s);
                s = fmaf(k1.x, qb.x, s); s = fmaf(k1.y, qb.y, s);
                s = fmaf(k1.z, qb.z, s); s = fmaf(k1.w, qb.w, s);
                s = fmaf(k2.x, qc.x, s); s = fmaf(k2.y, qc.y, s);
                s = fmaf(k2.z, qc.z, s); s = fmaf(k2.w, qc.w, s);
                s = fmaf(k3.x, qd.x, s); s = fmaf(k3.y, qd.y, s);
                s = fmaf(k3.z, qd.z, s); s = fmaf(k3.w, qd.w, s);
                s += __shfl_xor_sync(0xffffffffu, s, 1);
                s += __shfl_xor_sync(0xffffffffu, s, 2);
                if (valid && (lane & 3) == 0) xs[t] = s * 0.125f;
            }
            __syncthreads();
            float lmax = -1e30f;
            for (int t = tid; t < kvlen; t += 256) lmax = fmaxf(lmax, xs[t]);
            lmax = warpRedMax(lmax);
            if (lane == 0) s_red[w] = lmax;
            __syncthreads();
            float gm = s_red[0];
#pragma unroll
            for (int i = 1; i < 8; i++) gm = fmaxf(gm, s_red[i]);
            float ls = 0.f;
            for (int t = tid; t < kvlen; t += 256) {
                float p = __expf(xs[t] - gm);
                xs[t] = p;
                ls += p;
            }
            ls = warpRedSum(ls);
            if (lane == 0) s_red[8 + w] = ls;
            __syncthreads();
            float ssum = 0.f;
#pragma unroll
            for (int i = 0; i < 8; i++) ssum += s_red[8 + i];
            const float inv = 1.f / ssum;
            const int d = tid & 63, pt = tid >> 6;
            const float* vb = vc + (size_t)bb * CAP_ * 512 + h * 64 + d;
            float acc = 0.f;
            for (int t = pt; t < kvlen; t += 4)
                acc = fmaf(xs[t], vb[(size_t)t * 512], acc);
            s_part[tid] = acc;
            __syncthreads();
            if (pt == 0)
                at[bb * 512 + h * 64 + d] =
                    (s_part[d] + s_part[64 + d] + s_part[128 + d] + s_part[192 + d]) * inv;
        }
        gbar(target, tid);

        // ===== phase C: out-projection (N=512, K=512) -> t1 =====
        {
            const float4* src = (const float4*)(at + b0 * 512);
            float4* dst = (float4*)xs;
            for (int i = tid; i < 512; i += 256) dst[i] = src[i];
        }
        __syncthreads();
        {
            float a0, a1, a2, a3;
            dot4<4>(outW + (size_t)wg * 512, xs, 512, lane, a0, a1, a2, a3);
            if (lane == 0) {
                const float bv = outB[wg];
                t1[(b0 + 0) * 512 + wg] = a0 + bv;
                t1[(b0 + 1) * 512 + wg] = a1 + bv;
                t1[(b0 + 2) * 512 + wg] = a2 + bv;
                t1[(b0 + 3) * 512 + wg] = a3 + bv;
            }
        }
        gbar(target, tid);

        // ===== phase E: LN1 (warps 0-3, into s_ln) + FF1 (N=2048, relu) =====
        if (w < 4)
            warp_ln(t1 + (b0 + w) * 512, xt + (b0 + w) * 512,
                    ln1w, ln1b, s_ln + w * 512, lane);
        __syncthreads();
#pragma unroll
        for (int o = 0; o < 4; o++) {
            const int n = wg + o * 512;
            float a0, a1, a2, a3;
            dot4<4>(w1 + (size_t)n * 512, s_ln, 512, lane, a0, a1, a2, a3);
            if (lane == 0) {
                const float bv = b1[n];
                hfft[(b0 + 0) * 2048 + n] = fmaxf(a0 + bv, 0.f);
                hfft[(b0 + 1) * 2048 + n] = fmaxf(a1 + bv, 0.f);
                hfft[(b0 + 2) * 2048 + n] = fmaxf(a2 + bv, 0.f);
                hfft[(b0 + 3) * 2048 + n] = fmaxf(a3 + bv, 0.f);
            }
        }
        gbar(target, tid);

        // ===== phase F: FF2 (N=512, K=2048) -> t1 =====
        {
            const float4* src = (const float4*)(hfft + b0 * 2048);
            float4* dst = (float4*)xs;
            for (int i = tid; i < 2048; i += 256) dst[i] = src[i];
        }
        __syncthreads();
        {
            float a0, a1, a2, a3;
            dot4<16>(w2 + (size_t)wg * 2048, xs, 2048, lane, a0, a1, a2, a3);
            if (lane == 0) {
                const float bv = b2[wg];
                t1[(b0 + 0) * 512 + wg] = a0 + bv;
                t1[(b0 + 1) * 512 + wg] = a1 + bv;
                t1[(b0 + 2) * 512 + wg] = a2 + bv;
                t1[(b0 + 3) * 512 + wg] = a3 + bv;
            }
        }
        gbar(target, tid);
    }

    // final LN2 for the last step (s_ln still holds last step's LN1 rows)
    if ((bid == 0 || bid == 64) && w < 4)
        warp_ln(t1 + (b0 + w) * 512, s_ln + w * 512, ln2w, ln2b,
                out + ((size_t)(b0 + w) * CAP_ + (S_ + STEPS_ - 1)) * 512, lane);
}

// ---------------- host launcher ----------------
struct ScratchPtrs {
    float *Qkv, *Attn, *Pre, *Hb, *Hff, *Kc, *Vc, *Qt, *At, *Hfft, *T1;
};

static const ScratchPtrs& get_scratch() {
    static ScratchPtrs p;
    static bool init = false;
    if (!init) {
        cudaGetSymbolAddress((void**)&p.Qkv,  g_qkv);
        cudaGetSymbolAddress((void**)&p.Attn, g_attn);
        cudaGetSymbolAddress((void**)&p.Pre,  g_pre);
        cudaGetSymbolAddress((void**)&p.Hb,   g_h);
        cudaGetSymbolAddress((void**)&p.Hff,  g_hff);
        cudaGetSymbolAddress((void**)&p.Kc,   g_kc);
        cudaGetSymbolAddress((void**)&p.Vc,   g_vc);
        cudaGetSymbolAddress((void**)&p.Qt,   g_qt);
        cudaGetSymbolAddress((void**)&p.At,   g_at);
        cudaGetSymbolAddress((void**)&p.Hfft, g_hfft);
        cudaGetSymbolAddress((void**)&p.T1,   g_t1);
        cudaFuncSetAttribute(attn_prefill,
                             cudaFuncAttributeMaxDynamicSharedMemorySize, 49408);
        cudaFuncSetAttribute(decode_mega,
                             cudaFuncAttributeMaxDynamicSharedMemorySize, 32768);
        init = true;
    }
    return p;
}

extern "C" void kernel_launch(void* const* d_in, const int* in_sizes, int n_in,
                              void* d_out, int out_size)
{
    (void)in_sizes; (void)n_in; (void)out_size;
    const float* x    = (const float*)d_in[0];
    const float* dx   = (const float*)d_in[1];
    // d_in[2] = causal_mask (bool) — unused, causality computed analytically
    const float* qkvW = (const float*)d_in[3];
    const float* qkvB = (const float*)d_in[4];
    const float* outW = (const float*)d_in[5];
    const float* outB = (const float*)d_in[6];
    const float* w1   = (const float*)d_in[7];
    const float* b1   = (const float*)d_in[8];
    const float* w2   = (const float*)d_in[9];
    const float* b2   = (const float*)d_in[10];
    const float* ln1w = (const float*)d_in[11];
    const float* ln1b = (const float*)d_in[12];
    const float* ln2w = (const float*)d_in[13];
    const float* ln2b = (const float*)d_in[14];
    float* out = (float*)d_out;

    const ScratchPtrs& sp = get_scratch();

    // ---- prefill ----
    sgemm_nt<1,0,0><<<dim3(12, 64), 256>>>(x, qkvW, qkvB, nullptr, sp.Qkv, MTOK, 1536, 512);
    copy_kv<<<MTOK, 128>>>(sp.Qkv, sp.Kc, sp.Vc);
    attn_prefill<<<dim3(16, 64), 256, 49408>>>(sp.Qkv, sp.Attn);
    sgemm_nt<1,0,1><<<dim3(4, 64), 256>>>(sp.Attn, outW, outB, x, sp.Pre, MTOK, 512, 512);
    ln_rows<<<MTOK, 256>>>(sp.Pre, ln1w, ln1b, sp.Hb, 0);
    sgemm_nt<1,1,0><<<dim3(16, 64), 256>>>(sp.Hb, w1, b1, nullptr, sp.Hff, MTOK, 2048, 512);
    sgemm_nt<1,0,1><<<dim3(4, 64), 256>>>(sp.Hff, w2, b2, sp.Hb, sp.Pre, MTOK, 512, 2048);
    ln_rows<<<MTOK, 256>>>(sp.Pre, ln2w, ln2b, out, 64);

    // ---- decode: all 64 steps in one persistent launch ----
    decode_mega<<<NBLK, 256, 32768>>>(dx, qkvW, qkvB, outW, outB,
                                      w1, b1, w2, b2,
                                      ln1w, ln1b, ln2w, ln2b, out,
                                      sp.Qt, sp.Kc, sp.Vc, sp.At,
                                      sp.Hfft, sp.T1);
}

// round 5
// speedup vs baseline: 1.6234x; 1.0984x over previous
#include <cuda_runtime.h>
#include <cstdint>

#define B_     8
#define S_     1024
#define D_     512
#define H_     8
#define HD_    64
#define FF_    2048
#define STEPS_ 64
#define CAP_   1088
#define MTOK   (B_*S_)   /* 8192 */
#define NBLK   128

// ---------------- device scratch (no cudaMalloc allowed) ----------------
__device__ float g_qkv [MTOK*1536];   // prefill QKV
__device__ float g_attn[MTOK*D_];     // prefill attention output
__device__ float g_pre [MTOK*D_];     // pre-LN buffer
__device__ float g_h   [MTOK*D_];     // post-LN1 hidden
__device__ float g_hff [MTOK*FF_];    // MLP hidden
__device__ float g_kc  [B_*CAP_*D_];  // K cache
__device__ float g_vc  [B_*CAP_*D_];  // V cache
__device__ float g_qt  [B_*D_];       // decode q
__device__ float g_hfft[B_*FF_];      // decode MLP hidden
__device__ float g_t1  [B_*D_];       // decode temp
__device__ float g_op  [2*64*64];     // attn partial O   [part][b*8+h][64]
__device__ float g_ml  [2*64*2];      // attn partial m,l [part][b*8+h][2]
__device__ unsigned g_bar_count;      // central barrier arrivals
__device__ unsigned g_bar_sense;      // central barrier release sense

// ---------------- reductions ----------------
__device__ __forceinline__ float warpRedSum(float v) {
#pragma unroll
    for (int o = 16; o; o >>= 1) v += __shfl_xor_sync(0xffffffffu, v, o);
    return v;
}
__device__ __forceinline__ float warpRedMax(float v) {
#pragma unroll
    for (int o = 16; o; o >>= 1) v = fmaxf(v, __shfl_xor_sync(0xffffffffu, v, o));
    return v;
}

// ---------------- central barrier, load-based poll ----------------
__device__ __forceinline__ unsigned ld_acq(const unsigned* p) {
    unsigned v;
    asm volatile("ld.acquire.gpu.u32 %0, [%1];" : "=r"(v) : "l"(p) : "memory");
    return v;
}
__device__ __forceinline__ void st_rel(unsigned* p, unsigned v) {
    asm volatile("st.release.gpu.u32 [%0], %1;" :: "l"(p), "r"(v) : "memory");
}
__device__ __forceinline__ void gbar(unsigned& target, int tid) {
    __threadfence();
    __syncthreads();
    target += 1;
    if (tid == 0) {
        unsigned a = atomicAdd(&g_bar_count, 1u) + 1u;
        if (a == (unsigned)NBLK) {
            atomicExch(&g_bar_count, 0u);
            st_rel(&g_bar_sense, target);
        } else {
            while ((int)(ld_acq(&g_bar_sense) - target) < 0) { }
        }
    }
    __syncthreads();
    __threadfence();
}

// ---------------- SGEMM (NT), register-prefetch pipelined ----------------
// BM=BN=128, BK=16, 256 threads; 4+4 split tile; next tile's LDGs issued
// before compute so L2 latency hides under the 1024-FMA tile compute.
template<int BIAS, int RELU, int RES>
__global__ void __launch_bounds__(256, 2) sgemm_nt(
    const float* __restrict__ A, const float* __restrict__ Bm,
    const float* __restrict__ bias, const float* __restrict__ R,
    float* __restrict__ C, int M, int N, int K)
{
    __shared__ float As[16][132];
    __shared__ float Bs[16][132];
    const int tid = threadIdx.x;
    const int m0 = blockIdx.y * 128;
    const int n0 = blockIdx.x * 128;
    const int tx = tid & 15, ty = tid >> 4;
    const int r0 = ty * 4, c0 = tx * 4;
    const int lrow = tid >> 2;
    const int lk4  = (tid & 3) * 4;

    const float* Ap0 = A  + (size_t)(m0 + lrow)      * K + lk4;
    const float* Ap1 = A  + (size_t)(m0 + lrow + 64) * K + lk4;
    const float* Bp0 = Bm + (size_t)(n0 + lrow)      * K + lk4;
    const float* Bp1 = Bm + (size_t)(n0 + lrow + 64) * K + lk4;

    float acc[8][8];
#pragma unroll
    for (int i = 0; i < 8; i++)
#pragma unroll
        for (int j = 0; j < 8; j++) acc[i][j] = 0.f;

    float4 pa0 = *(const float4*)(Ap0);
    float4 pa1 = *(const float4*)(Ap1);
    float4 pb0 = *(const float4*)(Bp0);
    float4 pb1 = *(const float4*)(Bp1);

    for (int k0 = 0; k0 < K; k0 += 16) {
        As[lk4 + 0][lrow]      = pa0.x; As[lk4 + 1][lrow]      = pa0.y;
        As[lk4 + 2][lrow]      = pa0.z; As[lk4 + 3][lrow]      = pa0.w;
        As[lk4 + 0][lrow + 64] = pa1.x; As[lk4 + 1][lrow + 64] = pa1.y;
        As[lk4 + 2][lrow + 64] = pa1.z; As[lk4 + 3][lrow + 64] = pa1.w;
        Bs[lk4 + 0][lrow]      = pb0.x; Bs[lk4 + 1][lrow]      = pb0.y;
        Bs[lk4 + 2][lrow]      = pb0.z; Bs[lk4 + 3][lrow]      = pb0.w;
        Bs[lk4 + 0][lrow + 64] = pb1.x; Bs[lk4 + 1][lrow + 64] = pb1.y;
        Bs[lk4 + 2][lrow + 64] = pb1.z; Bs[lk4 + 3][lrow + 64] = pb1.w;
        __syncthreads();
        if (k0 + 16 < K) {   // prefetch next tile — latency hidden by compute
            pa0 = *(const float4*)(Ap0 + k0 + 16);
            pa1 = *(const float4*)(Ap1 + k0 + 16);
            pb0 = *(const float4*)(Bp0 + k0 + 16);
            pb1 = *(const float4*)(Bp1 + k0 + 16);
        }
#pragma unroll
        for (int kk = 0; kk < 16; kk++) {
            float af[8], bf[8];
            *(float4*)(af)     = *(const float4*)(&As[kk][r0]);
            *(float4*)(af + 4) = *(const float4*)(&As[kk][r0 + 64]);
            *(float4*)(bf)     = *(const float4*)(&Bs[kk][c0]);
            *(float4*)(bf + 4) = *(const float4*)(&Bs[kk][c0 + 64]);
#pragma unroll
            for (int i = 0; i < 8; i++)
#pragma unroll
                for (int j = 0; j < 8; j++)
                    acc[i][j] = fmaf(af[i], bf[j], acc[i][j]);
        }
        __syncthreads();
    }

    float bl[8];
#pragma unroll
    for (int j = 0; j < 8; j++)
        bl[j] = BIAS ? bias[n0 + c0 + (j < 4 ? j : 60 + j)] : 0.f;

#pragma unroll
    for (int i = 0; i < 8; i++) {
        const int row = m0 + r0 + (i < 4 ? i : 60 + i);
        const size_t rowoff = (size_t)row * N + n0;
#pragma unroll
        for (int jg = 0; jg < 2; jg++) {
            const int cb = c0 + jg * 64;
            float t0 = acc[i][jg * 4 + 0] + bl[jg * 4 + 0];
            float t1 = acc[i][jg * 4 + 1] + bl[jg * 4 + 1];
            float t2 = acc[i][jg * 4 + 2] + bl[jg * 4 + 2];
            float t3 = acc[i][jg * 4 + 3] + bl[jg * 4 + 3];
            if (RES) {
                float4 r = *(const float4*)(R + rowoff + cb);
                t0 += r.x; t1 += r.y; t2 += r.z; t3 += r.w;
            }
            if (RELU) {
                t0 = fmaxf(t0, 0.f); t1 = fmaxf(t1, 0.f);
                t2 = fmaxf(t2, 0.f); t3 = fmaxf(t3, 0.f);
            }
            float4 v; v.x = t0; v.y = t1; v.z = t2; v.w = t3;
            *(float4*)(C + rowoff + cb) = v;
        }
    }
}

// ---------------- prefill flash attention (causal), 64x64 tiles ----------------
__global__ void __launch_bounds__(256) attn_prefill(const float* __restrict__ qkv,
                                                    float* __restrict__ attn)
{
    extern __shared__ float sm[];
    float* Qs = sm;
    float* KP = sm + 64 * 64;
    float* Vs = KP + 64 * 65;

    const int b  = blockIdx.y >> 3;
    const int h  = blockIdx.y & 7;
    const int l0 = blockIdx.x * 64;
    const int tid = threadIdx.x;
    const int tx = tid & 15, ty = tid >> 4;
    const int r0 = ty * 4, c0 = tx * 4;

    const size_t rowbase = (size_t)(b * S_) * 1536;
    const float* qbase = qkv + rowbase + h * 64;
    const float* kbase = qkv + rowbase + 512 + h * 64;
    const float* vbase = qkv + rowbase + 1024 + h * 64;

    const int lt  = tid >> 4;
    const int ld4 = (tid & 15) * 4;

#pragma unroll
    for (int tt = lt; tt < 64; tt += 16) {
        float4 q4 = *(const float4*)(qbase + (size_t)(l0 + tt) * 1536 + ld4);
        Qs[(ld4 + 0) * 64 + tt] = q4.x;
        Qs[(ld4 + 1) * 64 + tt] = q4.y;
        Qs[(ld4 + 2) * 64 + tt] = q4.z;
        Qs[(ld4 + 3) * 64 + tt] = q4.w;
    }

    float o[4][4];
    float mrow[4], lrow[4];
#pragma unroll
    for (int i = 0; i < 4; i++) {
        mrow[i] = -1e30f; lrow[i] = 0.f;
#pragma unroll
        for (int j = 0; j < 4; j++) o[i][j] = 0.f;
    }

    const int ntiles = (l0 >> 6) + 1;
    for (int tile = 0; tile < ntiles; ++tile) {
        const int j0 = tile * 64;
        __syncthreads();
#pragma unroll
        for (int tt = lt; tt < 64; tt += 16) {
            float4 k4 = *(const float4*)(kbase + (size_t)(j0 + tt) * 1536 + ld4);
            KP[(ld4 + 0) * 65 + tt] = k4.x;
            KP[(ld4 + 1) * 65 + tt] = k4.y;
            KP[(ld4 + 2) * 65 + tt] = k4.z;
            KP[(ld4 + 3) * 65 + tt] = k4.w;
            float4 v4 = *(const float4*)(vbase + (size_t)(j0 + tt) * 1536 + ld4);
            *(float4*)(Vs + tt * 64 + ld4) = v4;
        }
        __syncthreads();

        float s[4][4];
#pragma unroll
        for (int i = 0; i < 4; i++)
#pragma unroll
            for (int j = 0; j < 4; j++) s[i][j] = 0.f;

        for (int d = 0; d < 64; d++) {
            float qf[4];
            *(float4*)qf = *(const float4*)(Qs + d * 64 + r0);
            float kf0 = KP[d * 65 + c0 + 0];
            float kf1 = KP[d * 65 + c0 + 1];
            float kf2 = KP[d * 65 + c0 + 2];
            float kf3 = KP[d * 65 + c0 + 3];
#pragma unroll
            for (int i = 0; i < 4; i++) {
                s[i][0] = fmaf(qf[i], kf0, s[i][0]);
                s[i][1] = fmaf(qf[i], kf1, s[i][1]);
                s[i][2] = fmaf(qf[i], kf2, s[i][2]);
                s[i][3] = fmaf(qf[i], kf3, s[i][3]);
            }
        }

        if (j0 == l0) {
#pragma unroll
            for (int i = 0; i < 4; i++)
#pragma unroll
                for (int j = 0; j < 4; j++)
                    s[i][j] = (j0 + c0 + j > l0 + r0 + i) ? -1e30f : s[i][j] * 0.125f;
        } else {
#pragma unroll
            for (int i = 0; i < 4; i++)
#pragma unroll
                for (int j = 0; j < 4; j++) s[i][j] *= 0.125f;
        }

        float p[4][4];
#pragma unroll
        for (int i = 0; i < 4; i++) {
            float rm = fmaxf(fmaxf(s[i][0], s[i][1]), fmaxf(s[i][2], s[i][3]));
#pragma unroll
            for (int off = 8; off; off >>= 1)
                rm = fmaxf(rm, __shfl_xor_sync(0xffffffffu, rm, off));
            float mnew  = fmaxf(mrow[i], rm);
            float alpha = __expf(mrow[i] - mnew);
            float ps = 0.f;
#pragma unroll
            for (int j = 0; j < 4; j++) { p[i][j] = __expf(s[i][j] - mnew); ps += p[i][j]; }
#pragma unroll
            for (int off = 8; off; off >>= 1)
                ps += __shfl_xor_sync(0xffffffffu, ps, off);
            lrow[i] = lrow[i] * alpha + ps;
            mrow[i] = mnew;
#pragma unroll
            for (int j = 0; j < 4; j++) o[i][j] *= alpha;
        }

        __syncthreads();
#pragma unroll
        for (int i = 0; i < 4; i++)
#pragma unroll
            for (int j = 0; j < 4; j++)
                KP[(r0 + i) * 65 + c0 + j] = p[i][j];
        __syncthreads();

        for (int c = 0; c < 64; c++) {
            float vv[4];
            *(float4*)vv = *(const float4*)(Vs + c * 64 + c0);
            float p0 = KP[(r0 + 0) * 65 + c];
            float p1 = KP[(r0 + 1) * 65 + c];
            float p2 = KP[(r0 + 2) * 65 + c];
            float p3 = KP[(r0 + 3) * 65 + c];
#pragma unroll
            for (int j = 0; j < 4; j++) {
                o[0][j] = fmaf(p0, vv[j], o[0][j]);
                o[1][j] = fmaf(p1, vv[j], o[1][j]);
                o[2][j] = fmaf(p2, vv[j], o[2][j]);
                o[3][j] = fmaf(p3, vv[j], o[3][j]);
            }
        }
    }

    float* ob = attn + (size_t)(b * S_ + l0) * 512 + h * 64;
#pragma unroll
    for (int i = 0; i < 4; i++) {
        float inv = 1.f / lrow[i];
        float4 v;
        v.x = o[i][0] * inv; v.y = o[i][1] * inv;
        v.z = o[i][2] * inv; v.w = o[i][3] * inv;
        *(float4*)(ob + (size_t)(r0 + i) * 512 + c0) = v;
    }
}

// ---------------- copy prefill K/V slices into the caches ----------------
__global__ void __launch_bounds__(128) copy_kv(const float* __restrict__ qkv,
                                               float* __restrict__ kc, float* __restrict__ vc)
{
    const int r = blockIdx.x;
    const int b = r >> 10, s = r & 1023;
    const int tid = threadIdx.x;
    const float4* src = (const float4*)(qkv + (size_t)r * 1536);
    float4* kd = (float4*)(kc + (size_t)(b * CAP_ + s) * 512);
    float4* vd = (float4*)(vc + (size_t)(b * CAP_ + s) * 512);
    kd[tid] = src[128 + tid];
    vd[tid] = src[256 + tid];
}

// ---------------- prefill LayerNorm over rows of 512 ----------------
__global__ void __launch_bounds__(256) ln_rows(const float* __restrict__ in,
                                               const float* __restrict__ g,
                                               const float* __restrict__ be,
                                               float* __restrict__ out, int outExtra)
{
    const int r = blockIdx.x;
    const int tid = threadIdx.x;
    const float* row = in + (size_t)r * 512;
    float v0 = row[tid], v1 = row[tid + 256];
    float s  = warpRedSum(v0 + v1);
    float s2 = warpRedSum(v0 * v0 + v1 * v1);
    __shared__ float r1[8], r2[8];
    __shared__ float smu, srs;
    const int w = tid >> 5, lane = tid & 31;
    if (lane == 0) { r1[w] = s; r2[w] = s2; }
    __syncthreads();
    if (tid == 0) {
        float S = 0.f, S2 = 0.f;
#pragma unroll
        for (int i = 0; i < 8; i++) { S += r1[i]; S2 += r2[i]; }
        float mu  = S * (1.f / 512.f);
        float var = S2 * (1.f / 512.f) - mu * mu;
        smu = mu; srs = rsqrtf(var + 1e-5f);
    }
    __syncthreads();
    const int orow = r + (r >> 10) * outExtra;
    float* od = out + (size_t)orow * 512;
    od[tid]       = (v0 - smu) * srs * g[tid]       + be[tid];
    od[tid + 256] = (v1 - smu) * srs * g[tid + 256] + be[tid + 256];
}

// ---------------- megakernel building blocks ----------------
template<int KP>
__device__ __forceinline__ void dot4(const float* __restrict__ wr,
                                     const float* xs, int Kstride, int lane,
                                     float& a0, float& a1, float& a2, float& a3)
{
    a0 = a1 = a2 = a3 = 0.f;
#pragma unroll
    for (int kp = 0; kp < KP; kp++) {
        const int k4 = kp * 128 + lane * 4;
        float4 wv = *(const float4*)(wr + k4);
        float4 x0 = *(const float4*)(xs + k4);
        float4 x1 = *(const float4*)(xs + Kstride + k4);
        float4 x2 = *(const float4*)(xs + 2 * Kstride + k4);
        float4 x3 = *(const float4*)(xs + 3 * Kstride + k4);
        a0 = fmaf(wv.x, x0.x, fmaf(wv.y, x0.y, fmaf(wv.z, x0.z, fmaf(wv.w, x0.w, a0))));
        a1 = fmaf(wv.x, x1.x, fmaf(wv.y, x1.y, fmaf(wv.z, x1.z, fmaf(wv.w, x1.w, a1))));
        a2 = fmaf(wv.x, x2.x, fmaf(wv.y, x2.y, fmaf(wv.z, x2.z, fmaf(wv.w, x2.w, a2))));
        a3 = fmaf(wv.x, x3.x, fmaf(wv.y, x3.y, fmaf(wv.z, x3.z, fmaf(wv.w, x3.w, a3))));
    }
    a0 = warpRedSum(a0); a1 = warpRedSum(a1);
    a2 = warpRedSum(a2); a3 = warpRedSum(a3);
}

__device__ __forceinline__ void warp_ln(const float* __restrict__ a,
                                        const float* __restrict__ r,
                                        const float* __restrict__ gw,
                                        const float* __restrict__ gb,
                                        float* __restrict__ o, int lane)
{
    float vals[16];
    float sv = 0.f, sq = 0.f;
#pragma unroll
    for (int g = 0; g < 4; g++) {
        const int idx = g * 128 + lane * 4;
        float4 av = *(const float4*)(a + idx);
        float4 rv = *(const float4*)(r + idx);
        float a0 = av.x + rv.x, a1 = av.y + rv.y;
        float a2 = av.z + rv.z, a3 = av.w + rv.w;
        vals[g * 4 + 0] = a0; vals[g * 4 + 1] = a1;
        vals[g * 4 + 2] = a2; vals[g * 4 + 3] = a3;
        sv += a0 + a1 + a2 + a3;
        sq += a0 * a0 + a1 * a1 + a2 * a2 + a3 * a3;
    }
    sv = warpRedSum(sv); sq = warpRedSum(sq);
    float mu = sv * (1.f / 512.f);
    float rs = rsqrtf(sq * (1.f / 512.f) - mu * mu + 1e-5f);
#pragma unroll
    for (int g = 0; g < 4; g++)
#pragma unroll
        for (int j = 0; j < 4; j++) {
            const int idx = g * 128 + lane * 4 + j;
            o[idx] = (vals[g * 4 + j] - mu) * rs * gw[idx] + gb[idx];
        }
}

// ---------------- decode megakernel: all 64 steps in one launch ----------------
__global__ void __launch_bounds__(256, 1) decode_mega(
    const float* __restrict__ dx,
    const float* __restrict__ qkvW, const float* __restrict__ qkvB,
    const float* __restrict__ outW, const float* __restrict__ outB,
    const float* __restrict__ w1, const float* __restrict__ b1,
    const float* __restrict__ w2, const float* __restrict__ b2,
    const float* __restrict__ ln1w, const float* __restrict__ ln1b,
    const float* __restrict__ ln2w, const float* __restrict__ ln2b,
    float* __restrict__ out,
    float* __restrict__ qt, float* __restrict__ kc, float* __restrict__ vc,
    float* __restrict__ hfft, float* __restrict__ t1,
    float* __restrict__ opart, float* __restrict__ mlpart)
{
    extern __shared__ float xs[];      // 8192 floats (32KB)
    __shared__ float s_ln[4 * 512];    // LN1 rows b0..b0+3 — persists to next step
    __shared__ float s_red[16];
    __shared__ float s_q[64];
    __shared__ float s_part[256];
    __shared__ float s_comb[128];
    __shared__ unsigned s_base;

    const int tid  = threadIdx.x;
    const int bid  = blockIdx.x;
    const int w    = tid >> 5, lane = tid & 31;
    const int half = bid >> 6;           // 0/1: 4-batch group
    const int b0   = half * 4;
    const int wg   = (bid & 63) * 8 + w; // 0..511

    if (tid == 0) s_base = ld_acq(&g_bar_sense);
    __syncthreads();
    unsigned target = s_base;

    for (int step = 0; step < STEPS_; step++) {
        const int cur = S_ + step;
        const float* xt = dx + (size_t)step * (B_ * D_);

        // ===== phase A: LN2(prev) on blocks 0 & 64 + QKV GEMV =====
        if (step > 0 && (bid == 0 || bid == 64) && w < 4)
            warp_ln(t1 + (b0 + w) * 512, s_ln + w * 512, ln2w, ln2b,
                    out + ((size_t)(b0 + w) * CAP_ + (cur - 1)) * 512, lane);
        {
            const float4* src = (const float4*)(xt + b0 * 512);
            float4* dst = (float4*)xs;
            for (int i = tid; i < 512; i += 256) dst[i] = src[i];
        }
        __syncthreads();
#pragma unroll
        for (int o = 0; o < 3; o++) {
            const int n = wg + o * 512;
            float a0, a1, a2, a3;
            dot4<4>(qkvW + (size_t)n * 512, xs, 512, lane, a0, a1, a2, a3);
            if (lane == 0) {
                const float bv = qkvB[n];
                if (o == 0) {
                    qt[(b0 + 0) * 512 + wg] = a0 + bv;
                    qt[(b0 + 1) * 512 + wg] = a1 + bv;
                    qt[(b0 + 2) * 512 + wg] = a2 + bv;
                    qt[(b0 + 3) * 512 + wg] = a3 + bv;
                } else if (o == 1) {
                    kc[((size_t)(b0 + 0) * CAP_ + cur) * 512 + wg] = a0 + bv;
                    kc[((size_t)(b0 + 1) * CAP_ + cur) * 512 + wg] = a1 + bv;
                    kc[((size_t)(b0 + 2) * CAP_ + cur) * 512 + wg] = a2 + bv;
                    kc[((size_t)(b0 + 3) * CAP_ + cur) * 512 + wg] = a3 + bv;
                } else {
                    vc[((size_t)(b0 + 0) * CAP_ + cur) * 512 + wg] = a0 + bv;
                    vc[((size_t)(b0 + 1) * CAP_ + cur) * 512 + wg] = a1 + bv;
                    vc[((size_t)(b0 + 2) * CAP_ + cur) * 512 + wg] = a2 + bv;
                    vc[((size_t)(b0 + 3) * CAP_ + cur) * 512 + wg] = a3 + bv;
                }
            }
        }
        gbar(target, tid);

        // ===== phase B: attention partials on ALL 128 blocks = (part, b, h) =====
        {
            const int part = bid >> 6;
            const int bb = (bid >> 3) & 7;
            const int h  = bid & 7;
            const int kvlen = cur + 1;
            const int hlen  = kvlen >> 1;
            const int tstart = part ? hlen : 0;
            const int tend   = part ? kvlen : hlen;
            if (tid < 64) s_q[tid] = qt[bb * 512 + h * 64 + tid];
            __syncthreads();
            const int tl = lane >> 2;
            const int kq = (lane & 3) * 16;
            const float4 qa = *(const float4*)(s_q + kq);
            const float4 qb = *(const float4*)(s_q + kq + 4);
            const float4 qc = *(const float4*)(s_q + kq + 8);
            const float4 qd = *(const float4*)(s_q + kq + 12);
            const float* kb = kc + (size_t)bb * CAP_ * 512 + h * 64;
            for (int t0 = tstart; t0 < tend; t0 += 64) {
                const int t = t0 + w * 8 + tl;
                const bool valid = t < tend;
                const float* kr = kb + (size_t)(valid ? t : tstart) * 512 + kq;
                float4 k0 = *(const float4*)(kr);
                float4 k1 = *(const float4*)(kr + 4);
                float4 k2 = *(const float4*)(kr + 8);
                float4 k3 = *(const float4*)(kr + 12);
                float s;
                s = k0.x * qa.x;
                s = fmaf(k0.y, qa.y, s); s = fmaf(k0.z, qa.z, s); s = fmaf(k0.w, qa.w, s);
                s = fmaf(k1.x, qb.x, s); s = fmaf(k1.y, qb.y, s);
                s = fmaf(k1.z, qb.z, s); s = fmaf(k1.w, qb.w, s);
                s = fmaf(k2.x, qc.x, s); s = fmaf(k2.y, qc.y, s);
                s = fmaf(k2.z, qc.z, s); s = fmaf(k2.w, qc.w, s);
                s = fmaf(k3.x, qd.x, s); s = fmaf(k3.y, qd.y, s);
                s = fmaf(k3.z, qd.z, s); s = fmaf(k3.w, qd.w, s);
                s += __shfl_xor_sync(0xffffffffu, s, 1);
                s += __shfl_xor_sync(0xffffffffu, s, 2);
                if (valid && (lane & 3) == 0) xs[t] = s * 0.125f;
            }
            __syncthreads();
            float lmax = -1e30f;
            for (int t = tstart + tid; t < tend; t += 256) lmax = fmaxf(lmax, xs[t]);
            lmax = warpRedMax(lmax);
            if (lane == 0) s_red[w] = lmax;
            __syncthreads();
            float gm = s_red[0];
#pragma unroll
            for (int i = 1; i < 8; i++) gm = fmaxf(gm, s_red[i]);
            float ls = 0.f;
            for (int t = tstart + tid; t < tend; t += 256) {
                float p = __expf(xs[t] - gm);
                xs[t] = p;
                ls += p;
            }
            ls = warpRedSum(ls);
            if (lane == 0) s_red[8 + w] = ls;
            __syncthreads();
            float ssum = 0.f;
#pragma unroll
            for (int i = 0; i < 8; i++) ssum += s_red[8 + i];
            const int d = tid & 63, pt = tid >> 6;
            const float* vb = vc + (size_t)bb * CAP_ * 512 + h * 64 + d;
            float vacc = 0.f;
            for (int t = tstart + pt; t < tend; t += 4)
                vacc = fmaf(xs[t], vb[(size_t)t * 512], vacc);
            s_part[tid] = vacc;
            __syncthreads();
            const int gi = part * 64 + bb * 8 + h;
            if (pt == 0)
                opart[gi * 64 + d] =
                    s_part[d] + s_part[64 + d] + s_part[128 + d] + s_part[192 + d];
            if (tid == 0) { mlpart[gi * 2] = gm; mlpart[gi * 2 + 1] = ssum; }
        }
        gbar(target, tid);

        // ===== phase C: combine attn parts for batches b0..b0+3, out-proj =====
        if (tid < 64) {
            float m1 = mlpart[tid * 2],        l1 = mlpart[tid * 2 + 1];
            float m2 = mlpart[(64 + tid) * 2], l2 = mlpart[(64 + tid) * 2 + 1];
            float gm = fmaxf(m1, m2);
            float e1 = __expf(m1 - gm), e2 = __expf(m2 - gm);
            float inv = 1.f / (e1 * l1 + e2 * l2);
            s_comb[tid * 2]     = e1 * inv;
            s_comb[tid * 2 + 1] = e2 * inv;
        }
        __syncthreads();
        for (int i = tid; i < 2048; i += 256) {
            const int b = b0 + (i >> 9);          // global batch
            const int col = i & 511;
            const int gi = b * 8 + (col >> 6);    // b*8+h
            const int d = col & 63;
            xs[i] = s_comb[gi * 2]     * opart[gi * 64 + d]
                  + s_comb[gi * 2 + 1] * opart[(64 + gi) * 64 + d];
        }
        __syncthreads();
        {
            float a0, a1, a2, a3;
            dot4<4>(outW + (size_t)wg * 512, xs, 512, lane, a0, a1, a2, a3);
            if (lane == 0) {
                const float bv = outB[wg];
                t1[(b0 + 0) * 512 + wg] = a0 + bv;
                t1[(b0 + 1) * 512 + wg] = a1 + bv;
                t1[(b0 + 2) * 512 + wg] = a2 + bv;
                t1[(b0 + 3) * 512 + wg] = a3 + bv;
            }
        }
        gbar(target, tid);

        // ===== phase E: LN1 (warps 0-3, into s_ln) + FF1 (N=2048, relu) =====
        if (w < 4)
            warp_ln(t1 + (b0 + w) * 512, xt + (b0 + w) * 512,
                    ln1w, ln1b, s_ln + w * 512, lane);
        __syncthreads();
#pragma unroll
        for (int o = 0; o < 4; o++) {
            const int n = wg + o * 512;
            float a0, a1, a2, a3;
            dot4<4>(w1 + (size_t)n * 512, s_ln, 512, lane, a0, a1, a2, a3);
            if (lane == 0) {
                const float bv = b1[n];
                hfft[(b0 + 0) * 2048 + n] = fmaxf(a0 + bv, 0.f);
                hfft[(b0 + 1) * 2048 + n] = fmaxf(a1 + bv, 0.f);
                hfft[(b0 + 2) * 2048 + n] = fmaxf(a2 + bv, 0.f);
                hfft[(b0 + 3) * 2048 + n] = fmaxf(a3 + bv, 0.f);
            }
        }
        gbar(target, tid);

        // ===== phase F: FF2 (N=512, K=2048) -> t1 =====
        {
            const float4* src = (const float4*)(hfft + b0 * 2048);
            float4* dst = (float4*)xs;
            for (int i = tid; i < 2048; i += 256) dst[i] = src[i];
        }
        __syncthreads();
        {
            float a0, a1, a2, a3;
            dot4<16>(w2 + (size_t)wg * 2048, xs, 2048, lane, a0, a1, a2, a3);
            if (lane == 0) {
                const float bv = b2[wg];
                t1[(b0 + 0) * 512 + wg] = a0 + bv;
                t1[(b0 + 1) * 512 + wg] = a1 + bv;
                t1[(b0 + 2) * 512 + wg] = a2 + bv;
                t1[(b0 + 3) * 512 + wg] = a3 + bv;
            }
        }
        gbar(target, tid);
    }

    // final LN2 for the last step
    if ((bid == 0 || bid == 64) && w < 4)
        warp_ln(t1 + (b0 + w) * 512, s_ln + w * 512, ln2w, ln2b,
                out + ((size_t)(b0 + w) * CAP_ + (S_ + STEPS_ - 1)) * 512, lane);
}

// ---------------- host launcher ----------------
struct ScratchPtrs {
    float *Qkv, *Attn, *Pre, *Hb, *Hff, *Kc, *Vc, *Qt, *Hfft, *T1, *Op, *Ml;
};

static const ScratchPtrs& get_scratch() {
    static ScratchPtrs p;
    static bool init = false;
    if (!init) {
        cudaGetSymbolAddress((void**)&p.Qkv,  g_qkv);
        cudaGetSymbolAddress((void**)&p.Attn, g_attn);
        cudaGetSymbolAddress((void**)&p.Pre,  g_pre);
        cudaGetSymbolAddress((void**)&p.Hb,   g_h);
        cudaGetSymbolAddress((void**)&p.Hff,  g_hff);
        cudaGetSymbolAddress((void**)&p.Kc,   g_kc);
        cudaGetSymbolAddress((void**)&p.Vc,   g_vc);
        cudaGetSymbolAddress((void**)&p.Qt,   g_qt);
        cudaGetSymbolAddress((void**)&p.Hfft, g_hfft);
        cudaGetSymbolAddress((void**)&p.T1,   g_t1);
        cudaGetSymbolAddress((void**)&p.Op,   g_op);
        cudaGetSymbolAddress((void**)&p.Ml,   g_ml);
        cudaFuncSetAttribute(attn_prefill,
                             cudaFuncAttributeMaxDynamicSharedMemorySize, 49408);
        cudaFuncSetAttribute(decode_mega,
                             cudaFuncAttributeMaxDynamicSharedMemorySize, 32768);
        init = true;
    }
    return p;
}

extern "C" void kernel_launch(void* const* d_in, const int* in_sizes, int n_in,
                              void* d_out, int out_size)
{
    (void)in_sizes; (void)n_in; (void)out_size;
    const float* x    = (const float*)d_in[0];
    const float* dx   = (const float*)d_in[1];
    // d_in[2] = causal_mask (bool) — unused, causality computed analytically
    const float* qkvW = (const float*)d_in[3];
    const float* qkvB = (const float*)d_in[4];
    const float* outW = (const float*)d_in[5];
    const float* outB = (const float*)d_in[6];
    const float* w1   = (const float*)d_in[7];
    const float* b1   = (const float*)d_in[8];
    const float* w2   = (const float*)d_in[9];
    const float* b2   = (const float*)d_in[10];
    const float* ln1w = (const float*)d_in[11];
    const float* ln1b = (const float*)d_in[12];
    const float* ln2w = (const float*)d_in[13];
    const float* ln2b = (const float*)d_in[14];
    float* out = (float*)d_out;

    const ScratchPtrs& sp = get_scratch();

    // ---- prefill ----
    sgemm_nt<1,0,0><<<dim3(12, 64), 256>>>(x, qkvW, qkvB, nullptr, sp.Qkv, MTOK, 1536, 512);
    copy_kv<<<MTOK, 128>>>(sp.Qkv, sp.Kc, sp.Vc);
    attn_prefill<<<dim3(16, 64), 256, 49408>>>(sp.Qkv, sp.Attn);
    sgemm_nt<1,0,1><<<dim3(4, 64), 256>>>(sp.Attn, outW, outB, x, sp.Pre, MTOK, 512, 512);
    ln_rows<<<MTOK, 256>>>(sp.Pre, ln1w, ln1b, sp.Hb, 0);
    sgemm_nt<1,1,0><<<dim3(16, 64), 256>>>(sp.Hb, w1, b1, nullptr, sp.Hff, MTOK, 2048, 512);
    sgemm_nt<1,0,1><<<dim3(4, 64), 256>>>(sp.Hff, w2, b2, sp.Hb, sp.Pre, MTOK, 512, 2048);
    ln_rows<<<MTOK, 256>>>(sp.Pre, ln2w, ln2b, out, 64);

    // ---- decode: all 64 steps in one persistent launch ----
    decode_mega<<<NBLK, 256, 32768>>>(dx, qkvW, qkvB, outW, outB,
                                      w1, b1, w2, b2,
                                      ln1w, ln1b, ln2w, ln2b, out,
                                      sp.Qt, sp.Kc, sp.Vc,
                                      sp.Hfft, sp.T1, sp.Op, sp.Ml);
}